// round 14
// baseline (speedup 1.0000x reference)
#include <cuda_runtime.h>
#include <cuda_fp16.h>
#include <math.h>
#include <stdint.h>

#define Bsz  2
#define Nseq 2048
#define Emb  1024
#define Hh   16
#define Dh   64
#define FFd  4096
#define Mrows (Bsz*Nseq)   // 4096

// ---------------- scratch (module globals; no runtime allocation) ----------
__device__ float  g_h  [Mrows*Emb];          // residual 1 (fp32)
__device__ float  g_h2 [Mrows*Emb];          // residual 2 (fp32)
__device__ __half g_hLh[Mrows*Emb];          // LN1 out (half)
__device__ __half g_qkv[3*(size_t)Mrows*Emb];// q(pre-scaled)/k/v planes [B,H,N,D]
__device__ __half g_ctxh[Mrows*Emb];         // attention out (half)
__device__ __half g_fh [Mrows*Emb];          // LN2 out (half)
__device__ __half g_ffnh[(size_t)Mrows*FFd]; // gelu out (half)
__device__ __half g_WqkvT[3*(size_t)Emb*Emb];// [n][k] K-major, q|k|v
__device__ __half g_WoT[Emb*Emb];
__device__ __half g_W1T[(size_t)Emb*FFd];
__device__ __half g_W2T[(size_t)FFd*Emb];
__device__ float  g_bqkv[3*Emb];

// =================== helpers ================================================
__device__ __forceinline__ uint32_t smem_u32(const void* p) {
    uint32_t a;
    asm("{ .reg .u64 t; cvta.to.shared.u64 t, %1; cvt.u32.u64 %0, t; }"
        : "=r"(a) : "l"(p));
    return a;
}
__device__ __forceinline__ void cp16(uint32_t dst, const void* src) {
    asm volatile("cp.async.cg.shared.global [%0], [%1], 16;" :: "r"(dst), "l"(src));
}
__device__ __forceinline__ void mma_fp16(float d[4], const uint32_t a[4],
                                         const uint32_t b[2]) {
    asm volatile(
        "mma.sync.aligned.m16n8k16.row.col.f32.f16.f16.f32 "
        "{%0,%1,%2,%3}, {%4,%5,%6,%7}, {%8,%9}, {%0,%1,%2,%3};"
        : "+f"(d[0]), "+f"(d[1]), "+f"(d[2]), "+f"(d[3])
        : "r"(a[0]), "r"(a[1]), "r"(a[2]), "r"(a[3]), "r"(b[0]), "r"(b[1]));
}
__device__ __forceinline__ uint32_t packh2(float x, float y) {
    __half2 h = __floats2half2_rn(x, y);
    return *(uint32_t*)&h;
}
__device__ __forceinline__ void ldsm_x4(uint32_t& r0, uint32_t& r1,
                                        uint32_t& r2, uint32_t& r3,
                                        uint32_t addr) {
    asm volatile("ldmatrix.sync.aligned.m8n8.x4.shared.b16 "
                 "{%0,%1,%2,%3}, [%4];"
                 : "=r"(r0), "=r"(r1), "=r"(r2), "=r"(r3) : "r"(addr));
}
__device__ __forceinline__ void ldsm_x4_t(uint32_t& r0, uint32_t& r1,
                                          uint32_t& r2, uint32_t& r3,
                                          uint32_t addr) {
    asm volatile("ldmatrix.sync.aligned.m8n8.x4.trans.shared.b16 "
                 "{%0,%1,%2,%3}, [%4];"
                 : "=r"(r0), "=r"(r1), "=r"(r2), "=r"(r3) : "r"(addr));
}

// ========== fp16 mma GEMM: 64x64 CTA, 128 thr, 2-stage, 8 CTA/SM ============
// C[M,N] = A[M,K](half) @ Bt^T(half,[N,K] K-major) + bias(fp32)
// MODE 1: gelu -> half    MODE 2: +res -> fp32    MODE 3: qkv scatter -> half
#define SROWH 40   // halfs per smem row (BK 32 + pad 8); ldsm conflict-free
#define ABUF  (64 * SROWH)                  // A halfs per stage
#define BBUF  (64 * SROWH)                  // B halfs per stage
#define GEMM_SMEM (2 * (ABUF + BBUF) * 2)   // 20480 bytes -> 8 CTAs/SM

template<int MODE>
__global__ __launch_bounds__(128, 8) void gemm_h(
    const __half* __restrict__ A, const __half* __restrict__ Bt,
    const float* __restrict__ bias, const float* __restrict__ res,
    void* __restrict__ Cv, int M, int N, int K)
{
    extern __shared__ __half gsm[];
    __half* sA = gsm;                 // [2][ABUF]
    __half* sB = gsm + 2 * ABUF;      // [2][BBUF]

    const int tid  = threadIdx.x;
    const int wid  = tid >> 5;         // 0..3
    const int lane = tid & 31;
    const int gid  = lane >> 2;
    const int tig  = lane & 3;
    const int m_w  = (wid & 1) * 32;   // 2 m-warps
    const int n_w  = (wid >> 1) * 32;  // 2 n-warps
    const int m0   = blockIdx.y * 64;
    const int n0   = blockIdx.x * 64;

    const __half* Ab = A  + (size_t)m0 * K;
    const __half* Bb = Bt + (size_t)n0 * K;

    // loaders: A and B each 64 rows x 4 segs = 256 cp16, 2/thread each
    const int lr = tid >> 2;           // rows lr and lr+32
    const int ls = tid & 3;            // 8-half segment

    const int lrow  = lane & 15;        // ldmatrix row within 16
    const int lcolh = (lane >> 4) * 8;  // ldmatrix col offset (halfs)

    const uint32_t sA0 = smem_u32(sA);
    const uint32_t sB0 = smem_u32(sB);
    const uint32_t stgA = ABUF * 2;
    const uint32_t stgBy = BBUF * 2;

    float acc[2][4][4] = {};
    const int nk = K >> 5;              // BK = 32 halfs

    // ---- prologue: prefetch chunk 0 into stage 0 --------------------------
    #pragma unroll
    for (int j = 0; j < 2; ++j) {
        const int r = lr + j * 32;
        cp16(sA0 + (r * SROWH + ls * 8) * 2, Ab + (size_t)r * K + ls * 8);
        cp16(sB0 + (r * SROWH + ls * 8) * 2, Bb + (size_t)r * K + ls * 8);
    }
    asm volatile("cp.async.commit_group;");

    for (int c = 0; c < nk; ++c) {
        asm volatile("cp.async.wait_group 0;");
        __syncthreads();

        if (c + 1 < nk) {
            const int kk = (c + 1) << 5;
            const uint32_t da = sA0 + (uint32_t)((c + 1) & 1) * stgA;
            const uint32_t db = sB0 + (uint32_t)((c + 1) & 1) * stgBy;
            #pragma unroll
            for (int j = 0; j < 2; ++j) {
                const int r = lr + j * 32;
                cp16(da + (r * SROWH + ls * 8) * 2, Ab + (size_t)r * K + kk + ls * 8);
                cp16(db + (r * SROWH + ls * 8) * 2, Bb + (size_t)r * K + kk + ls * 8);
            }
            asm volatile("cp.async.commit_group;");
        }

        const uint32_t aB = sA0 + (uint32_t)(c & 1) * stgA;
        const uint32_t bB = sB0 + (uint32_t)(c & 1) * stgBy;

        #pragma unroll
        for (int ks = 0; ks < 2; ++ks) {            // two k16 steps per chunk
            const int kh = ks * 16 + lcolh;
            uint32_t ua[2][4];
            #pragma unroll
            for (int mt = 0; mt < 2; ++mt)
                ldsm_x4(ua[mt][0], ua[mt][1], ua[mt][2], ua[mt][3],
                        aB + ((m_w + mt * 16 + lrow) * SROWH + kh) * 2);
            uint32_t ub[4][2];
            #pragma unroll
            for (int ntp = 0; ntp < 2; ++ntp) {
                uint32_t r0, r1, r2, r3;
                ldsm_x4(r0, r1, r2, r3,
                        bB + ((n_w + ntp * 16 + lrow) * SROWH + kh) * 2);
                ub[2*ntp    ][0] = r0; ub[2*ntp    ][1] = r2;
                ub[2*ntp + 1][0] = r1; ub[2*ntp + 1][1] = r3;
            }
            #pragma unroll
            for (int mt = 0; mt < 2; ++mt)
                #pragma unroll
                for (int nt = 0; nt < 4; ++nt)
                    mma_fp16(acc[mt][nt], ua[mt], ub[nt]);
        }
    }

    #pragma unroll
    for (int mt = 0; mt < 2; ++mt) {
        const int row = m0 + m_w + mt * 16 + gid;
        #pragma unroll
        for (int nt = 0; nt < 4; ++nt) {
            const int col = n0 + n_w + nt * 8 + tig * 2;
            float2 b2 = *(const float2*)(bias + col);
            #pragma unroll
            for (int hf = 0; hf < 2; ++hf) {
                const int r = row + hf * 8;
                float vx = acc[mt][nt][hf * 2 + 0] + b2.x;
                float vy = acc[mt][nt][hf * 2 + 1] + b2.y;
                if (MODE == 1) {
                    vx = 0.5f * vx * (1.0f + erff(vx * 0.70710678118654752f));
                    vy = 0.5f * vy * (1.0f + erff(vy * 0.70710678118654752f));
                    *(__half2*)((__half*)Cv + (size_t)r * N + col)
                        = __floats2half2_rn(vx, vy);
                }
                if (MODE == 2) {
                    float2 r2 = *(const float2*)(res + (size_t)r * N + col);
                    float2 o; o.x = vx + r2.x; o.y = vy + r2.y;
                    *(float2*)((float*)Cv + (size_t)r * N + col) = o;
                }
                if (MODE == 3) {
                    const int which = col >> 10;
                    const int cc = col & 1023;
                    const int hh = cc >> 6, dd = cc & 63;
                    if (which == 0) { vx *= 0.03125f; vy *= 0.03125f; }
                    const int b = r >> 11, n = r & 2047;
                    __half* dst = (__half*)Cv +
                        (((size_t)((which * Bsz + b) * Hh + hh)) * Nseq + n) * Dh + dd;
                    *(__half2*)dst = __floats2half2_rn(vx, vy);
                }
            }
        }
    }
}

// =================== fused flash attention (fp16 mma) =======================
// qkv planes (half): q pre-scaled by 1/32. out: ctx (half) [B,N,E].
#define KSTR  72   // halfs per smem row
#define KSTRW 36
#define FL_SMEM ((2*64 + 2*64 + 128) * KSTR * 2)   // 55296 bytes

__global__ __launch_bounds__(256, 2) void flash_h(
    const __half* __restrict__ QKV, __half* __restrict__ ctx)
{
    extern __shared__ __half smh[];
    __half* sK = smh;                    // [2][64*KSTR]
    __half* sV = smh + 2 * 64 * KSTR;    // [2][64*KSTR]
    __half* sQ = smh + 4 * 64 * KSTR;    // [128*KSTR]

    const int tid  = threadIdx.x;
    const int wid  = tid >> 5;
    const int lane = tid & 31;
    const int gid  = lane >> 2;
    const int tig  = lane & 3;
    const int bh   = blockIdx.y;
    const int b    = bh >> 4;
    const int hh   = bh & 15;
    const int m0   = blockIdx.x * 128;

    const size_t PLN = (size_t)Bsz * Hh * Nseq * Dh;
    const __half* Qb = QKV           + ((size_t)bh * Nseq + m0) * Dh;
    const __half* Kb = QKV + PLN     + (size_t)bh * Nseq * Dh;
    const __half* Vb = QKV + 2 * PLN + (size_t)bh * Nseq * Dh;

    // stage Q tile (128 x 64 halfs)
    #pragma unroll
    for (int i = 0; i < 4; ++i) {
        const int idx = i * 256 + tid;
        const int r = idx >> 3, sg = idx & 7;
        *(float4*)(sQ + r * KSTR + sg * 8) = *(const float4*)(Qb + r * Dh + sg * 8);
    }
    __syncthreads();

    uint32_t uq[4][4];
    {
        const uint32_t* q_s = (const uint32_t*)sQ + (wid * 16) * KSTRW;
        #pragma unroll
        for (int ks = 0; ks < 4; ++ks) {
            const int kw = ks * 8;
            uq[ks][0] = q_s[ gid      * KSTRW + kw + tig    ];
            uq[ks][1] = q_s[(gid + 8) * KSTRW + kw + tig    ];
            uq[ks][2] = q_s[ gid      * KSTRW + kw + tig + 4];
            uq[ks][3] = q_s[(gid + 8) * KSTRW + kw + tig + 4];
        }
    }
    __syncthreads();

    float oacc[8][4] = {};
    float mrun[2] = {-1e30f, -1e30f};
    float lrun[2] = {0.0f, 0.0f};

    const uint32_t sK0 = smem_u32(sK);
    const uint32_t sV0 = smem_u32(sV);
    const uint32_t tileB = 64 * KSTR * 2;

    // K/V tile loader: 64 rows x 64 halfs, 2 x 16B per thread per tile
    {
        #pragma unroll
        for (int j = 0; j < 2; ++j) {
            const int idx = j * 256 + tid;
            const int r = idx >> 3, sg = idx & 7;
            cp16(sK0 + (r * KSTR + sg * 8) * 2, Kb + (size_t)r * Dh + sg * 8);
            cp16(sV0 + (r * KSTR + sg * 8) * 2, Vb + (size_t)r * Dh + sg * 8);
        }
        asm volatile("cp.async.commit_group;");
    }

    const int niter = Nseq / 64;
    for (int it = 0; it < niter; ++it) {
        const int buf = it & 1;
        if (it + 1 < niter) {
            const uint32_t dk = sK0 + (uint32_t)((it + 1) & 1) * tileB;
            const uint32_t dv = sV0 + (uint32_t)((it + 1) & 1) * tileB;
            const __half* Kn = Kb + (size_t)(it + 1) * 64 * Dh;
            const __half* Vn = Vb + (size_t)(it + 1) * 64 * Dh;
            #pragma unroll
            for (int j = 0; j < 2; ++j) {
                const int idx = j * 256 + tid;
                const int r = idx >> 3, sg = idx & 7;
                cp16(dk + (r * KSTR + sg * 8) * 2, Kn + (size_t)r * Dh + sg * 8);
                cp16(dv + (r * KSTR + sg * 8) * 2, Vn + (size_t)r * Dh + sg * 8);
            }
            asm volatile("cp.async.commit_group;");
            asm volatile("cp.async.wait_group 1;");
        } else {
            asm volatile("cp.async.wait_group 0;");
        }
        __syncthreads();

        const uint32_t* k_s = (const uint32_t*)(sK + buf * 64 * KSTR);
        const uint32_t  vb  = sV0 + (uint32_t)buf * tileB;

        // ---- S = (Q/32) @ K^T  (scale pre-folded into Q) -----------------
        float sacc[8][4] = {};
        #pragma unroll
        for (int ks = 0; ks < 4; ++ks) {
            const int kw = ks * 8;
            uint32_t ub[8][2];
            #pragma unroll
            for (int nt = 0; nt < 8; ++nt) {
                const int rn = nt * 8 + gid;
                ub[nt][0] = k_s[rn * KSTRW + kw + tig    ];
                ub[nt][1] = k_s[rn * KSTRW + kw + tig + 4];
            }
            #pragma unroll
            for (int nt = 0; nt < 8; ++nt)
                mma_fp16(sacc[nt], uq[ks], ub[nt]);
        }

        // ---- online softmax ----------------------------------------------
        float rm0 = -1e30f, rm1 = -1e30f;
        #pragma unroll
        for (int nt = 0; nt < 8; ++nt) {
            rm0 = fmaxf(rm0, fmaxf(sacc[nt][0], sacc[nt][1]));
            rm1 = fmaxf(rm1, fmaxf(sacc[nt][2], sacc[nt][3]));
        }
        rm0 = fmaxf(rm0, __shfl_xor_sync(0xffffffff, rm0, 1));
        rm0 = fmaxf(rm0, __shfl_xor_sync(0xffffffff, rm0, 2));
        rm1 = fmaxf(rm1, __shfl_xor_sync(0xffffffff, rm1, 1));
        rm1 = fmaxf(rm1, __shfl_xor_sync(0xffffffff, rm1, 2));

        const float mn0 = fmaxf(mrun[0], rm0);
        const float mn1 = fmaxf(mrun[1], rm1);
        const float cor0 = __expf(mrun[0] - mn0);
        const float cor1 = __expf(mrun[1] - mn1);
        mrun[0] = mn0; mrun[1] = mn1;

        float rs0 = 0.0f, rs1 = 0.0f;
        #pragma unroll
        for (int nt = 0; nt < 8; ++nt) {
            sacc[nt][0] = __expf(sacc[nt][0] - mn0);
            sacc[nt][1] = __expf(sacc[nt][1] - mn0);
            sacc[nt][2] = __expf(sacc[nt][2] - mn1);
            sacc[nt][3] = __expf(sacc[nt][3] - mn1);
            rs0 += sacc[nt][0] + sacc[nt][1];
            rs1 += sacc[nt][2] + sacc[nt][3];
        }
        rs0 += __shfl_xor_sync(0xffffffff, rs0, 1);
        rs0 += __shfl_xor_sync(0xffffffff, rs0, 2);
        rs1 += __shfl_xor_sync(0xffffffff, rs1, 1);
        rs1 += __shfl_xor_sync(0xffffffff, rs1, 2);

        lrun[0] = lrun[0] * cor0 + rs0;
        lrun[1] = lrun[1] * cor1 + rs1;
        #pragma unroll
        for (int dt = 0; dt < 8; ++dt) {
            oacc[dt][0] *= cor0; oacc[dt][1] *= cor0;
            oacc[dt][2] *= cor1; oacc[dt][3] *= cor1;
        }

        // ---- O += P @ V : P C-frags repacked as A-frags in registers -------
        #pragma unroll
        for (int ks2 = 0; ks2 < 4; ++ks2) {
            uint32_t pa[4];
            pa[0] = packh2(sacc[2*ks2    ][0], sacc[2*ks2    ][1]);
            pa[1] = packh2(sacc[2*ks2    ][2], sacc[2*ks2    ][3]);
            pa[2] = packh2(sacc[2*ks2 + 1][0], sacc[2*ks2 + 1][1]);
            pa[3] = packh2(sacc[2*ks2 + 1][2], sacc[2*ks2 + 1][3]);
            const int t  = lane >> 3;
            const int rr = lane & 7;
            #pragma unroll
            for (int ntp = 0; ntp < 4; ++ntp) {
                const uint32_t addr = vb +
                    ((ks2 * 16 + (t & 1) * 8 + rr) * KSTR + ntp * 16 + (t >> 1) * 8) * 2;
                uint32_t r0, r1, r2, r3;
                ldsm_x4_t(r0, r1, r2, r3, addr);
                uint32_t bb0[2] = {r0, r1};
                uint32_t bb1[2] = {r2, r3};
                mma_fp16(oacc[2*ntp    ], pa, bb0);
                mma_fp16(oacc[2*ntp + 1], pa, bb1);
            }
        }
        __syncthreads();
    }

    // ---- epilogue: O /= l -> half, write ctx [B,N,E] -------------------------
    const float li0 = 1.0f / lrun[0];
    const float li1 = 1.0f / lrun[1];
    const int row0 = m0 + wid * 16 + gid;
    #pragma unroll
    for (int dt = 0; dt < 8; ++dt) {
        const int col = hh * Dh + dt * 8 + tig * 2;
        *(__half2*)(ctx + ((size_t)(b * Nseq + row0    )) * Emb + col)
            = __floats2half2_rn(oacc[dt][0] * li0, oacc[dt][1] * li0);
        *(__half2*)(ctx + ((size_t)(b * Nseq + row0 + 8)) * Emb + col)
            = __floats2half2_rn(oacc[dt][2] * li1, oacc[dt][3] * li1);
    }
}

// =================== weight transposes (fp32 -> half, [n][k]) ===============
__global__ void transpose_h(const float* __restrict__ W,
                            __half* __restrict__ Wt, int K, int N)
{
    __shared__ float tile[32][33];
    const int n0 = blockIdx.x * 32, k0 = blockIdx.y * 32;
    const int tx = threadIdx.x, ty = threadIdx.y;  // 32 x 8
    #pragma unroll
    for (int i = 0; i < 32; i += 8)
        tile[ty + i][tx] = W[(size_t)(k0 + ty + i) * N + n0 + tx];
    __syncthreads();
    #pragma unroll
    for (int i = 0; i < 32; i += 8)
        Wt[(size_t)(n0 + ty + i) * K + k0 + tx] = __float2half_rn(tile[tx][ty + i]);
}

__global__ void transpose_qkv(const float* __restrict__ Wq,
                              const float* __restrict__ Wk,
                              const float* __restrict__ Wv,
                              __half* __restrict__ Wt)
{
    const float* W = blockIdx.z == 0 ? Wq : (blockIdx.z == 1 ? Wk : Wv);
    __half* dst = Wt + (size_t)blockIdx.z * Emb * Emb;
    __shared__ float tile[32][33];
    const int n0 = blockIdx.x * 32, k0 = blockIdx.y * 32;
    const int tx = threadIdx.x, ty = threadIdx.y;
    #pragma unroll
    for (int i = 0; i < 32; i += 8)
        tile[ty + i][tx] = W[(size_t)(k0 + ty + i) * Emb + n0 + tx];
    __syncthreads();
    #pragma unroll
    for (int i = 0; i < 32; i += 8)
        dst[(size_t)(n0 + ty + i) * Emb + k0 + tx] = __float2half_rn(tile[tx][ty + i]);
}

__global__ void biascat_kernel(const float* __restrict__ bq,
                               const float* __restrict__ bk,
                               const float* __restrict__ bv,
                               float* __restrict__ dst)
{
    const int i = blockIdx.x * 256 + threadIdx.x;
    dst[i] = i < 1024 ? bq[i] : (i < 2048 ? bk[i - 1024] : bv[i - 2048]);
}

// ---------------- block-wide mean/var via warp shuffles ---------------------
__device__ __forceinline__ void blk_meanvar(float s, float q, int tid,
                                            float& mean, float& var)
{
    __shared__ float ws[8], wq[8];
    #pragma unroll
    for (int o = 16; o > 0; o >>= 1) {
        s += __shfl_xor_sync(0xffffffff, s, o);
        q += __shfl_xor_sync(0xffffffff, q, o);
    }
    if ((tid & 31) == 0) { ws[tid >> 5] = s; wq[tid >> 5] = q; }
    __syncthreads();
    float ss = ws[tid & 7], qq = wq[tid & 7];
    #pragma unroll
    for (int o = 4; o > 0; o >>= 1) {
        ss += __shfl_xor_sync(0xffffffff, ss, o);
        qq += __shfl_xor_sync(0xffffffff, qq, o);
    }
    mean = ss * (1.0f / Emb);
    var  = qq * (1.0f / Emb) - mean * mean;
}

// ---------------- input proj (K=2) + LayerNorm ------------------------------
__global__ void input_ln_kernel(const float* __restrict__ x,
                                const float* __restrict__ Wi,
                                const float* __restrict__ bi,
                                const float* __restrict__ gamma,
                                const float* __restrict__ beta,
                                float* __restrict__ h,
                                __half* __restrict__ hL)
{
    const int m = blockIdx.x;
    const int t = threadIdx.x;
    const float x0 = x[m*2+0];
    const float x1 = x[m*2+1];
    const int c = t*4;

    float4 w0 = *(const float4*)(Wi + c);
    float4 w1 = *(const float4*)(Wi + Emb + c);
    float4 bb = *(const float4*)(bi + c);

    float v0 = fmaf(x0,w0.x, fmaf(x1,w1.x, bb.x));
    float v1 = fmaf(x0,w0.y, fmaf(x1,w1.y, bb.y));
    float v2 = fmaf(x0,w0.z, fmaf(x1,w1.z, bb.z));
    float v3 = fmaf(x0,w0.w, fmaf(x1,w1.w, bb.w));

    *(float4*)(h + (size_t)m*Emb + c) = make_float4(v0,v1,v2,v3);

    float mean, var;
    blk_meanvar(v0+v1+v2+v3, v0*v0+v1*v1+v2*v2+v3*v3, t, mean, var);
    const float rs = rsqrtf(var + 1e-5f);

    float4 g4 = *(const float4*)(gamma + c);
    float4 b4 = *(const float4*)(beta  + c);
    __half* dst = hL + (size_t)m*Emb + c;
    *(__half2*)(dst    ) = __floats2half2_rn((v0-mean)*rs*g4.x + b4.x,
                                             (v1-mean)*rs*g4.y + b4.y);
    *(__half2*)(dst + 2) = __floats2half2_rn((v2-mean)*rs*g4.z + b4.z,
                                             (v3-mean)*rs*g4.w + b4.w);
}

// ---------------- LayerNorm (fp32 in -> half out) ----------------------------
__global__ void ln_kernel(const float* __restrict__ X,
                          const float* __restrict__ gamma,
                          const float* __restrict__ beta,
                          __half* __restrict__ Y)
{
    const int m = blockIdx.x;
    const int t = threadIdx.x;
    const int c = t*4;
    float4 v = *(const float4*)(X + (size_t)m*Emb + c);

    float mean, var;
    blk_meanvar(v.x+v.y+v.z+v.w, v.x*v.x+v.y*v.y+v.z*v.z+v.w*v.w, t, mean, var);
    const float rs = rsqrtf(var + 1e-5f);

    float4 g4 = *(const float4*)(gamma + c);
    float4 b4 = *(const float4*)(beta  + c);
    __half* dst = Y + (size_t)m*Emb + c;
    *(__half2*)(dst    ) = __floats2half2_rn((v.x-mean)*rs*g4.x + b4.x,
                                             (v.y-mean)*rs*g4.y + b4.y);
    *(__half2*)(dst + 2) = __floats2half2_rn((v.z-mean)*rs*g4.z + b4.z,
                                             (v.w-mean)*rs*g4.w + b4.w);
}

// ---------------- launch ----------------------------------------------------
extern "C" void kernel_launch(void* const* d_in, const int* in_sizes, int n_in,
                              void* d_out, int out_size)
{
    (void)in_sizes; (void)n_in; (void)out_size;
    const float* x     = (const float*)d_in[0];
    const float* W_in  = (const float*)d_in[1];
    const float* b_in  = (const float*)d_in[2];
    const float* gamma = (const float*)d_in[3];
    const float* beta  = (const float*)d_in[4];
    const float* Wq    = (const float*)d_in[5];
    const float* bq    = (const float*)d_in[6];
    const float* Wk    = (const float*)d_in[7];
    const float* bk    = (const float*)d_in[8];
    const float* Wv    = (const float*)d_in[9];
    const float* bv    = (const float*)d_in[10];
    const float* Wo    = (const float*)d_in[11];
    const float* bo    = (const float*)d_in[12];
    const float* W1    = (const float*)d_in[13];
    const float* b1    = (const float*)d_in[14];
    const float* W2    = (const float*)d_in[15];
    const float* b2    = (const float*)d_in[16];
    float* out = (float*)d_out;

    float  *h, *h2, *bqkv;
    __half *hLh, *qkv, *ctxh, *fh, *ffnh, *WqkvT, *WoT, *W1T, *W2T;
    cudaGetSymbolAddress((void**)&h,     g_h);
    cudaGetSymbolAddress((void**)&h2,    g_h2);
    cudaGetSymbolAddress((void**)&bqkv,  g_bqkv);
    cudaGetSymbolAddress((void**)&hLh,   g_hLh);
    cudaGetSymbolAddress((void**)&qkv,   g_qkv);
    cudaGetSymbolAddress((void**)&ctxh,  g_ctxh);
    cudaGetSymbolAddress((void**)&fh,    g_fh);
    cudaGetSymbolAddress((void**)&ffnh,  g_ffnh);
    cudaGetSymbolAddress((void**)&WqkvT, g_WqkvT);
    cudaGetSymbolAddress((void**)&WoT,   g_WoT);
    cudaGetSymbolAddress((void**)&W1T,   g_W1T);
    cudaGetSymbolAddress((void**)&W2T,   g_W2T);

    cudaFuncSetAttribute(flash_h,
        cudaFuncAttributeMaxDynamicSharedMemorySize, FL_SMEM);
    cudaFuncSetAttribute(gemm_h<1>,
        cudaFuncAttributeMaxDynamicSharedMemorySize, GEMM_SMEM);
    cudaFuncSetAttribute(gemm_h<2>,
        cudaFuncAttributeMaxDynamicSharedMemorySize, GEMM_SMEM);
    cudaFuncSetAttribute(gemm_h<3>,
        cudaFuncAttributeMaxDynamicSharedMemorySize, GEMM_SMEM);

    dim3 tb(32, 8);

    // 0: input projection + pre-attn LN
    input_ln_kernel<<<Mrows, 256>>>(x, W_in, b_in, gamma, beta, h, hLh);
    // 1: bias concat
    biascat_kernel<<<12, 256>>>(bq, bk, bv, bqkv);
    // 2: qkv weight transpose (fused)
    transpose_qkv<<<dim3(32, 32, 3), tb>>>(Wq, Wk, Wv, WqkvT);
    // 3: fused QKV projection (ncu target)
    gemm_h<3><<<dim3(3*Emb/64, Mrows/64), 128, GEMM_SMEM>>>(
        hLh, WqkvT, bqkv, nullptr, qkv, Mrows, 3*Emb, Emb);
    // 4: fused flash attention -> ctx (half)
    flash_h<<<dim3(Nseq/128, Bsz*Hh), 256, FL_SMEM>>>(qkv, ctxh);
    // 5: Wo transpose
    transpose_h<<<dim3(Emb/32, Emb/32), tb>>>(Wo, WoT, Emb, Emb);
    // 6: O projection + residual (fp32 out)
    gemm_h<2><<<dim3(Emb/64, Mrows/64), 128, GEMM_SMEM>>>(
        ctxh, WoT, bo, h, h2, Mrows, Emb, Emb);
    // 7: LN -> f (half)
    ln_kernel<<<Mrows, 256>>>(h2, gamma, beta, fh);
    // 8: W1 transpose
    transpose_h<<<dim3(FFd/32, Emb/32), tb>>>(W1, W1T, Emb, FFd);
    // 9: FFN1 + gelu (half out)
    gemm_h<1><<<dim3(FFd/64, Mrows/64), 128, GEMM_SMEM>>>(
        fh, W1T, b1, nullptr, ffnh, Mrows, FFd, Emb);
    // 10: W2 transpose
    transpose_h<<<dim3(Emb/32, FFd/32), tb>>>(W2, W2T, FFd, Emb);
    // 11: FFN2 + residual (fp32 out)
    gemm_h<2><<<dim3(Emb/64, Mrows/64), 128, GEMM_SMEM>>>(
        ffnh, W2T, b2, h2, out, Mrows, Emb, FFd);
}

// round 15
// speedup vs baseline: 1.0212x; 1.0212x over previous
#include <cuda_runtime.h>
#include <cuda_fp16.h>
#include <math.h>
#include <stdint.h>

#define Bsz  2
#define Nseq 2048
#define Emb  1024
#define Hh   16
#define Dh   64
#define FFd  4096
#define Mrows (Bsz*Nseq)   // 4096

// ---------------- scratch (module globals; no runtime allocation) ----------
__device__ float  g_h  [Mrows*Emb];          // residual 1 (fp32)
__device__ float  g_h2 [Mrows*Emb];          // residual 2 (fp32)
__device__ __half g_hLh[Mrows*Emb];          // LN1 out (half)
__device__ __half g_qkv[3*(size_t)Mrows*Emb];// q(pre-scaled)/k/v planes [B,H,N,D]
__device__ __half g_ctxh[Mrows*Emb];         // attention out (half)
__device__ __half g_fh [Mrows*Emb];          // LN2 out (half)
__device__ __half g_ffnh[(size_t)Mrows*FFd]; // gelu out (half)
__device__ __half g_WqkvT[3*(size_t)Emb*Emb];// [n][k] K-major, q|k|v
__device__ __half g_WoT[Emb*Emb];
__device__ __half g_W1T[(size_t)Emb*FFd];
__device__ __half g_W2T[(size_t)FFd*Emb];
__device__ float  g_bqkv[3*Emb];

// =================== helpers ================================================
__device__ __forceinline__ uint32_t smem_u32(const void* p) {
    uint32_t a;
    asm("{ .reg .u64 t; cvta.to.shared.u64 t, %1; cvt.u32.u64 %0, t; }"
        : "=r"(a) : "l"(p));
    return a;
}
__device__ __forceinline__ void cp16(uint32_t dst, const void* src) {
    asm volatile("cp.async.cg.shared.global [%0], [%1], 16;" :: "r"(dst), "l"(src));
}
__device__ __forceinline__ void mma_fp16(float d[4], const uint32_t a[4],
                                         const uint32_t b[2]) {
    asm volatile(
        "mma.sync.aligned.m16n8k16.row.col.f32.f16.f16.f32 "
        "{%0,%1,%2,%3}, {%4,%5,%6,%7}, {%8,%9}, {%0,%1,%2,%3};"
        : "+f"(d[0]), "+f"(d[1]), "+f"(d[2]), "+f"(d[3])
        : "r"(a[0]), "r"(a[1]), "r"(a[2]), "r"(a[3]), "r"(b[0]), "r"(b[1]));
}
__device__ __forceinline__ uint32_t packh2(float x, float y) {
    __half2 h = __floats2half2_rn(x, y);
    return *(uint32_t*)&h;
}
__device__ __forceinline__ void ldsm_x4(uint32_t& r0, uint32_t& r1,
                                        uint32_t& r2, uint32_t& r3,
                                        uint32_t addr) {
    asm volatile("ldmatrix.sync.aligned.m8n8.x4.shared.b16 "
                 "{%0,%1,%2,%3}, [%4];"
                 : "=r"(r0), "=r"(r1), "=r"(r2), "=r"(r3) : "r"(addr));
}
__device__ __forceinline__ void ldsm_x4_t(uint32_t& r0, uint32_t& r1,
                                          uint32_t& r2, uint32_t& r3,
                                          uint32_t addr) {
    asm volatile("ldmatrix.sync.aligned.m8n8.x4.trans.shared.b16 "
                 "{%0,%1,%2,%3}, [%4];"
                 : "=r"(r0), "=r"(r1), "=r"(r2), "=r"(r3) : "r"(addr));
}

// ====== fp16 mma GEMM: 64x128 CTA, 128 thr, 32x64 warp tiles, 4 CTA/SM ======
// C[M,N] = A[M,K](half) @ Bt^T(half,[N,K] K-major) + bias(fp32)
// MODE 1: gelu -> half    MODE 2: +res -> fp32    MODE 3: qkv scatter -> half
#define SROWH 40   // halfs per smem row (BK 32 + pad 8); ldsm conflict-free
#define ABUF  (64  * SROWH)                 // A halfs per stage
#define BBUF  (128 * SROWH)                 // B halfs per stage
#define GEMM_SMEM (3 * (ABUF + BBUF) * 2)   // 46080 bytes -> 4 CTAs/SM

template<int MODE>
__global__ __launch_bounds__(128, 4) void gemm_h(
    const __half* __restrict__ A, const __half* __restrict__ Bt,
    const float* __restrict__ bias, const float* __restrict__ res,
    void* __restrict__ Cv, int M, int N, int K)
{
    extern __shared__ __half gsm[];
    __half* sA = gsm;                 // [3][ABUF]
    __half* sB = gsm + 3 * ABUF;      // [3][BBUF]

    const int tid  = threadIdx.x;
    const int wid  = tid >> 5;         // 0..3
    const int lane = tid & 31;
    const int gid  = lane >> 2;
    const int tig  = lane & 3;
    const int m_w  = (wid & 1) * 32;   // 2 m-warps
    const int n_w  = (wid >> 1) * 64;  // 2 n-warps (64-wide tiles)
    const int m0   = blockIdx.y * 64;
    const int n0   = blockIdx.x * 128;

    const __half* Ab = A  + (size_t)m0 * K;
    const __half* Bb = Bt + (size_t)n0 * K;

    // loaders: A 64 rows x 4 segs (2/thread), B 128 rows x 4 segs (4/thread)
    const int lr = tid >> 2;           // base row
    const int ls = tid & 3;            // 8-half segment

    const int lrow  = lane & 15;        // ldmatrix row within 16
    const int lcolh = (lane >> 4) * 8;  // ldmatrix col offset (halfs)

    const uint32_t sA0 = smem_u32(sA);
    const uint32_t sB0 = smem_u32(sB);
    const uint32_t stgA = ABUF * 2;
    const uint32_t stgBy = BBUF * 2;

    float acc[2][8][4] = {};
    const int nk = K >> 5;              // BK = 32 halfs

    // ---- prologue: prefetch chunks 0 and 1 --------------------------------
    #pragma unroll
    for (int p = 0; p < 2; ++p) {
        const int kk = p << 5;
        const uint32_t da = sA0 + (uint32_t)p * stgA;
        const uint32_t db = sB0 + (uint32_t)p * stgBy;
        #pragma unroll
        for (int j = 0; j < 2; ++j) {
            const int r = lr + j * 32;
            cp16(da + (r * SROWH + ls * 8) * 2, Ab + (size_t)r * K + kk + ls * 8);
        }
        #pragma unroll
        for (int j = 0; j < 4; ++j) {
            const int r = lr + j * 32;
            cp16(db + (r * SROWH + ls * 8) * 2, Bb + (size_t)r * K + kk + ls * 8);
        }
        asm volatile("cp.async.commit_group;");
    }

    int stg = 0;
    for (int c = 0; c < nk; ++c) {
        if (c + 1 < nk) { asm volatile("cp.async.wait_group 1;"); }
        else            { asm volatile("cp.async.wait_group 0;"); }
        __syncthreads();

        if (c + 2 < nk) {
            const int kk = (c + 2) << 5;
            const int ns = (stg + 2 >= 3) ? stg - 1 : stg + 2;
            const uint32_t da = sA0 + (uint32_t)ns * stgA;
            const uint32_t db = sB0 + (uint32_t)ns * stgBy;
            #pragma unroll
            for (int j = 0; j < 2; ++j) {
                const int r = lr + j * 32;
                cp16(da + (r * SROWH + ls * 8) * 2, Ab + (size_t)r * K + kk + ls * 8);
            }
            #pragma unroll
            for (int j = 0; j < 4; ++j) {
                const int r = lr + j * 32;
                cp16(db + (r * SROWH + ls * 8) * 2, Bb + (size_t)r * K + kk + ls * 8);
            }
            asm volatile("cp.async.commit_group;");
        }

        const uint32_t aB = sA0 + (uint32_t)stg * stgA;
        const uint32_t bB = sB0 + (uint32_t)stg * stgBy;

        #pragma unroll
        for (int ks = 0; ks < 2; ++ks) {            // two k16 steps per chunk
            const int kh = ks * 16 + lcolh;
            uint32_t ua[2][4];
            #pragma unroll
            for (int mt = 0; mt < 2; ++mt)
                ldsm_x4(ua[mt][0], ua[mt][1], ua[mt][2], ua[mt][3],
                        aB + ((m_w + mt * 16 + lrow) * SROWH + kh) * 2);
            uint32_t ub[8][2];
            #pragma unroll
            for (int ntp = 0; ntp < 4; ++ntp) {
                uint32_t r0, r1, r2, r3;
                ldsm_x4(r0, r1, r2, r3,
                        bB + ((n_w + ntp * 16 + lrow) * SROWH + kh) * 2);
                ub[2*ntp    ][0] = r0; ub[2*ntp    ][1] = r2;
                ub[2*ntp + 1][0] = r1; ub[2*ntp + 1][1] = r3;
            }
            #pragma unroll
            for (int mt = 0; mt < 2; ++mt)
                #pragma unroll
                for (int nt = 0; nt < 8; ++nt)
                    mma_fp16(acc[mt][nt], ua[mt], ub[nt]);
        }
        stg = (stg + 1 >= 3) ? 0 : stg + 1;
    }

    #pragma unroll
    for (int mt = 0; mt < 2; ++mt) {
        const int row = m0 + m_w + mt * 16 + gid;
        #pragma unroll
        for (int nt = 0; nt < 8; ++nt) {
            const int col = n0 + n_w + nt * 8 + tig * 2;
            float2 b2 = *(const float2*)(bias + col);
            #pragma unroll
            for (int hf = 0; hf < 2; ++hf) {
                const int r = row + hf * 8;
                float vx = acc[mt][nt][hf * 2 + 0] + b2.x;
                float vy = acc[mt][nt][hf * 2 + 1] + b2.y;
                if (MODE == 1) {
                    vx = 0.5f * vx * (1.0f + erff(vx * 0.70710678118654752f));
                    vy = 0.5f * vy * (1.0f + erff(vy * 0.70710678118654752f));
                    *(__half2*)((__half*)Cv + (size_t)r * N + col)
                        = __floats2half2_rn(vx, vy);
                }
                if (MODE == 2) {
                    float2 r2 = *(const float2*)(res + (size_t)r * N + col);
                    float2 o; o.x = vx + r2.x; o.y = vy + r2.y;
                    *(float2*)((float*)Cv + (size_t)r * N + col) = o;
                }
                if (MODE == 3) {
                    const int which = col >> 10;
                    const int cc = col & 1023;
                    const int hh = cc >> 6, dd = cc & 63;
                    if (which == 0) { vx *= 0.03125f; vy *= 0.03125f; }
                    const int b = r >> 11, n = r & 2047;
                    __half* dst = (__half*)Cv +
                        (((size_t)((which * Bsz + b) * Hh + hh)) * Nseq + n) * Dh + dd;
                    *(__half2*)dst = __floats2half2_rn(vx, vy);
                }
            }
        }
    }
}

// =================== fused flash attention (fp16 mma) =======================
// qkv planes (half): q pre-scaled by 1/32. out: ctx (half) [B,N,E].
#define KSTR  72   // halfs per smem row
#define KSTRW 36
#define FL_SMEM ((2*64 + 2*64 + 128) * KSTR * 2)   // 55296 bytes

__global__ __launch_bounds__(256, 2) void flash_h(
    const __half* __restrict__ QKV, __half* __restrict__ ctx)
{
    extern __shared__ __half smh[];
    __half* sK = smh;                    // [2][64*KSTR]
    __half* sV = smh + 2 * 64 * KSTR;    // [2][64*KSTR]
    __half* sQ = smh + 4 * 64 * KSTR;    // [128*KSTR]

    const int tid  = threadIdx.x;
    const int wid  = tid >> 5;
    const int lane = tid & 31;
    const int gid  = lane >> 2;
    const int tig  = lane & 3;
    const int bh   = blockIdx.y;
    const int b    = bh >> 4;
    const int hh   = bh & 15;
    const int m0   = blockIdx.x * 128;

    const size_t PLN = (size_t)Bsz * Hh * Nseq * Dh;
    const __half* Qb = QKV           + ((size_t)bh * Nseq + m0) * Dh;
    const __half* Kb = QKV + PLN     + (size_t)bh * Nseq * Dh;
    const __half* Vb = QKV + 2 * PLN + (size_t)bh * Nseq * Dh;

    // stage Q tile (128 x 64 halfs)
    #pragma unroll
    for (int i = 0; i < 4; ++i) {
        const int idx = i * 256 + tid;
        const int r = idx >> 3, sg = idx & 7;
        *(float4*)(sQ + r * KSTR + sg * 8) = *(const float4*)(Qb + r * Dh + sg * 8);
    }
    __syncthreads();

    uint32_t uq[4][4];
    {
        const uint32_t* q_s = (const uint32_t*)sQ + (wid * 16) * KSTRW;
        #pragma unroll
        for (int ks = 0; ks < 4; ++ks) {
            const int kw = ks * 8;
            uq[ks][0] = q_s[ gid      * KSTRW + kw + tig    ];
            uq[ks][1] = q_s[(gid + 8) * KSTRW + kw + tig    ];
            uq[ks][2] = q_s[ gid      * KSTRW + kw + tig + 4];
            uq[ks][3] = q_s[(gid + 8) * KSTRW + kw + tig + 4];
        }
    }
    __syncthreads();

    float oacc[8][4] = {};
    float mrun[2] = {-1e30f, -1e30f};
    float lrun[2] = {0.0f, 0.0f};

    const uint32_t sK0 = smem_u32(sK);
    const uint32_t sV0 = smem_u32(sV);
    const uint32_t tileB = 64 * KSTR * 2;

    // K/V tile loader: 64 rows x 64 halfs, 2 x 16B per thread per tile
    {
        #pragma unroll
        for (int j = 0; j < 2; ++j) {
            const int idx = j * 256 + tid;
            const int r = idx >> 3, sg = idx & 7;
            cp16(sK0 + (r * KSTR + sg * 8) * 2, Kb + (size_t)r * Dh + sg * 8);
            cp16(sV0 + (r * KSTR + sg * 8) * 2, Vb + (size_t)r * Dh + sg * 8);
        }
        asm volatile("cp.async.commit_group;");
    }

    const int niter = Nseq / 64;
    for (int it = 0; it < niter; ++it) {
        const int buf = it & 1;
        if (it + 1 < niter) {
            const uint32_t dk = sK0 + (uint32_t)((it + 1) & 1) * tileB;
            const uint32_t dv = sV0 + (uint32_t)((it + 1) & 1) * tileB;
            const __half* Kn = Kb + (size_t)(it + 1) * 64 * Dh;
            const __half* Vn = Vb + (size_t)(it + 1) * 64 * Dh;
            #pragma unroll
            for (int j = 0; j < 2; ++j) {
                const int idx = j * 256 + tid;
                const int r = idx >> 3, sg = idx & 7;
                cp16(dk + (r * KSTR + sg * 8) * 2, Kn + (size_t)r * Dh + sg * 8);
                cp16(dv + (r * KSTR + sg * 8) * 2, Vn + (size_t)r * Dh + sg * 8);
            }
            asm volatile("cp.async.commit_group;");
            asm volatile("cp.async.wait_group 1;");
        } else {
            asm volatile("cp.async.wait_group 0;");
        }
        __syncthreads();

        const uint32_t* k_s = (const uint32_t*)(sK + buf * 64 * KSTR);
        const uint32_t  vb  = sV0 + (uint32_t)buf * tileB;

        // ---- S = (Q/32) @ K^T  (scale pre-folded into Q) -----------------
        float sacc[8][4] = {};
        #pragma unroll
        for (int ks = 0; ks < 4; ++ks) {
            const int kw = ks * 8;
            uint32_t ub[8][2];
            #pragma unroll
            for (int nt = 0; nt < 8; ++nt) {
                const int rn = nt * 8 + gid;
                ub[nt][0] = k_s[rn * KSTRW + kw + tig    ];
                ub[nt][1] = k_s[rn * KSTRW + kw + tig + 4];
            }
            #pragma unroll
            for (int nt = 0; nt < 8; ++nt)
                mma_fp16(sacc[nt], uq[ks], ub[nt]);
        }

        // ---- online softmax ----------------------------------------------
        float rm0 = -1e30f, rm1 = -1e30f;
        #pragma unroll
        for (int nt = 0; nt < 8; ++nt) {
            rm0 = fmaxf(rm0, fmaxf(sacc[nt][0], sacc[nt][1]));
            rm1 = fmaxf(rm1, fmaxf(sacc[nt][2], sacc[nt][3]));
        }
        rm0 = fmaxf(rm0, __shfl_xor_sync(0xffffffff, rm0, 1));
        rm0 = fmaxf(rm0, __shfl_xor_sync(0xffffffff, rm0, 2));
        rm1 = fmaxf(rm1, __shfl_xor_sync(0xffffffff, rm1, 1));
        rm1 = fmaxf(rm1, __shfl_xor_sync(0xffffffff, rm1, 2));

        const float mn0 = fmaxf(mrun[0], rm0);
        const float mn1 = fmaxf(mrun[1], rm1);
        const float cor0 = __expf(mrun[0] - mn0);
        const float cor1 = __expf(mrun[1] - mn1);
        mrun[0] = mn0; mrun[1] = mn1;

        float rs0 = 0.0f, rs1 = 0.0f;
        #pragma unroll
        for (int nt = 0; nt < 8; ++nt) {
            sacc[nt][0] = __expf(sacc[nt][0] - mn0);
            sacc[nt][1] = __expf(sacc[nt][1] - mn0);
            sacc[nt][2] = __expf(sacc[nt][2] - mn1);
            sacc[nt][3] = __expf(sacc[nt][3] - mn1);
            rs0 += sacc[nt][0] + sacc[nt][1];
            rs1 += sacc[nt][2] + sacc[nt][3];
        }
        rs0 += __shfl_xor_sync(0xffffffff, rs0, 1);
        rs0 += __shfl_xor_sync(0xffffffff, rs0, 2);
        rs1 += __shfl_xor_sync(0xffffffff, rs1, 1);
        rs1 += __shfl_xor_sync(0xffffffff, rs1, 2);

        lrun[0] = lrun[0] * cor0 + rs0;
        lrun[1] = lrun[1] * cor1 + rs1;
        #pragma unroll
        for (int dt = 0; dt < 8; ++dt) {
            oacc[dt][0] *= cor0; oacc[dt][1] *= cor0;
            oacc[dt][2] *= cor1; oacc[dt][3] *= cor1;
        }

        // ---- O += P @ V : P C-frags repacked as A-frags in registers -------
        #pragma unroll
        for (int ks2 = 0; ks2 < 4; ++ks2) {
            uint32_t pa[4];
            pa[0] = packh2(sacc[2*ks2    ][0], sacc[2*ks2    ][1]);
            pa[1] = packh2(sacc[2*ks2    ][2], sacc[2*ks2    ][3]);
            pa[2] = packh2(sacc[2*ks2 + 1][0], sacc[2*ks2 + 1][1]);
            pa[3] = packh2(sacc[2*ks2 + 1][2], sacc[2*ks2 + 1][3]);
            const int t  = lane >> 3;
            const int rr = lane & 7;
            #pragma unroll
            for (int ntp = 0; ntp < 4; ++ntp) {
                const uint32_t addr = vb +
                    ((ks2 * 16 + (t & 1) * 8 + rr) * KSTR + ntp * 16 + (t >> 1) * 8) * 2;
                uint32_t r0, r1, r2, r3;
                ldsm_x4_t(r0, r1, r2, r3, addr);
                uint32_t bb0[2] = {r0, r1};
                uint32_t bb1[2] = {r2, r3};
                mma_fp16(oacc[2*ntp    ], pa, bb0);
                mma_fp16(oacc[2*ntp + 1], pa, bb1);
            }
        }
        __syncthreads();
    }

    // ---- epilogue: O /= l -> half, write ctx [B,N,E] -------------------------
    const float li0 = 1.0f / lrun[0];
    const float li1 = 1.0f / lrun[1];
    const int row0 = m0 + wid * 16 + gid;
    #pragma unroll
    for (int dt = 0; dt < 8; ++dt) {
        const int col = hh * Dh + dt * 8 + tig * 2;
        *(__half2*)(ctx + ((size_t)(b * Nseq + row0    )) * Emb + col)
            = __floats2half2_rn(oacc[dt][0] * li0, oacc[dt][1] * li0);
        *(__half2*)(ctx + ((size_t)(b * Nseq + row0 + 8)) * Emb + col)
            = __floats2half2_rn(oacc[dt][2] * li1, oacc[dt][3] * li1);
    }
}

// =================== weight transposes (fp32 -> half, [n][k]) ===============
__global__ void transpose_h(const float* __restrict__ W,
                            __half* __restrict__ Wt, int K, int N)
{
    __shared__ float tile[32][33];
    const int n0 = blockIdx.x * 32, k0 = blockIdx.y * 32;
    const int tx = threadIdx.x, ty = threadIdx.y;  // 32 x 8
    #pragma unroll
    for (int i = 0; i < 32; i += 8)
        tile[ty + i][tx] = W[(size_t)(k0 + ty + i) * N + n0 + tx];
    __syncthreads();
    #pragma unroll
    for (int i = 0; i < 32; i += 8)
        Wt[(size_t)(n0 + ty + i) * K + k0 + tx] = __float2half_rn(tile[tx][ty + i]);
}

__global__ void transpose_qkv(const float* __restrict__ Wq,
                              const float* __restrict__ Wk,
                              const float* __restrict__ Wv,
                              __half* __restrict__ Wt)
{
    const float* W = blockIdx.z == 0 ? Wq : (blockIdx.z == 1 ? Wk : Wv);
    __half* dst = Wt + (size_t)blockIdx.z * Emb * Emb;
    __shared__ float tile[32][33];
    const int n0 = blockIdx.x * 32, k0 = blockIdx.y * 32;
    const int tx = threadIdx.x, ty = threadIdx.y;
    #pragma unroll
    for (int i = 0; i < 32; i += 8)
        tile[ty + i][tx] = W[(size_t)(k0 + ty + i) * Emb + n0 + tx];
    __syncthreads();
    #pragma unroll
    for (int i = 0; i < 32; i += 8)
        dst[(size_t)(n0 + ty + i) * Emb + k0 + tx] = __float2half_rn(tile[tx][ty + i]);
}

__global__ void biascat_kernel(const float* __restrict__ bq,
                               const float* __restrict__ bk,
                               const float* __restrict__ bv,
                               float* __restrict__ dst)
{
    const int i = blockIdx.x * 256 + threadIdx.x;
    dst[i] = i < 1024 ? bq[i] : (i < 2048 ? bk[i - 1024] : bv[i - 2048]);
}

// ---------------- block-wide mean/var via warp shuffles ---------------------
__device__ __forceinline__ void blk_meanvar(float s, float q, int tid,
                                            float& mean, float& var)
{
    __shared__ float ws[8], wq[8];
    #pragma unroll
    for (int o = 16; o > 0; o >>= 1) {
        s += __shfl_xor_sync(0xffffffff, s, o);
        q += __shfl_xor_sync(0xffffffff, q, o);
    }
    if ((tid & 31) == 0) { ws[tid >> 5] = s; wq[tid >> 5] = q; }
    __syncthreads();
    float ss = ws[tid & 7], qq = wq[tid & 7];
    #pragma unroll
    for (int o = 4; o > 0; o >>= 1) {
        ss += __shfl_xor_sync(0xffffffff, ss, o);
        qq += __shfl_xor_sync(0xffffffff, qq, o);
    }
    mean = ss * (1.0f / Emb);
    var  = qq * (1.0f / Emb) - mean * mean;
}

// ---------------- input proj (K=2) + LayerNorm ------------------------------
__global__ void input_ln_kernel(const float* __restrict__ x,
                                const float* __restrict__ Wi,
                                const float* __restrict__ bi,
                                const float* __restrict__ gamma,
                                const float* __restrict__ beta,
                                float* __restrict__ h,
                                __half* __restrict__ hL)
{
    const int m = blockIdx.x;
    const int t = threadIdx.x;
    const float x0 = x[m*2+0];
    const float x1 = x[m*2+1];
    const int c = t*4;

    float4 w0 = *(const float4*)(Wi + c);
    float4 w1 = *(const float4*)(Wi + Emb + c);
    float4 bb = *(const float4*)(bi + c);

    float v0 = fmaf(x0,w0.x, fmaf(x1,w1.x, bb.x));
    float v1 = fmaf(x0,w0.y, fmaf(x1,w1.y, bb.y));
    float v2 = fmaf(x0,w0.z, fmaf(x1,w1.z, bb.z));
    float v3 = fmaf(x0,w0.w, fmaf(x1,w1.w, bb.w));

    *(float4*)(h + (size_t)m*Emb + c) = make_float4(v0,v1,v2,v3);

    float mean, var;
    blk_meanvar(v0+v1+v2+v3, v0*v0+v1*v1+v2*v2+v3*v3, t, mean, var);
    const float rs = rsqrtf(var + 1e-5f);

    float4 g4 = *(const float4*)(gamma + c);
    float4 b4 = *(const float4*)(beta  + c);
    __half* dst = hL + (size_t)m*Emb + c;
    *(__half2*)(dst    ) = __floats2half2_rn((v0-mean)*rs*g4.x + b4.x,
                                             (v1-mean)*rs*g4.y + b4.y);
    *(__half2*)(dst + 2) = __floats2half2_rn((v2-mean)*rs*g4.z + b4.z,
                                             (v3-mean)*rs*g4.w + b4.w);
}

// ---------------- LayerNorm (fp32 in -> half out) ----------------------------
__global__ void ln_kernel(const float* __restrict__ X,
                          const float* __restrict__ gamma,
                          const float* __restrict__ beta,
                          __half* __restrict__ Y)
{
    const int m = blockIdx.x;
    const int t = threadIdx.x;
    const int c = t*4;
    float4 v = *(const float4*)(X + (size_t)m*Emb + c);

    float mean, var;
    blk_meanvar(v.x+v.y+v.z+v.w, v.x*v.x+v.y*v.y+v.z*v.z+v.w*v.w, t, mean, var);
    const float rs = rsqrtf(var + 1e-5f);

    float4 g4 = *(const float4*)(gamma + c);
    float4 b4 = *(const float4*)(beta  + c);
    __half* dst = Y + (size_t)m*Emb + c;
    *(__half2*)(dst    ) = __floats2half2_rn((v.x-mean)*rs*g4.x + b4.x,
                                             (v.y-mean)*rs*g4.y + b4.y);
    *(__half2*)(dst + 2) = __floats2half2_rn((v.z-mean)*rs*g4.z + b4.z,
                                             (v.w-mean)*rs*g4.w + b4.w);
}

// ---------------- launch ----------------------------------------------------
extern "C" void kernel_launch(void* const* d_in, const int* in_sizes, int n_in,
                              void* d_out, int out_size)
{
    (void)in_sizes; (void)n_in; (void)out_size;
    const float* x     = (const float*)d_in[0];
    const float* W_in  = (const float*)d_in[1];
    const float* b_in  = (const float*)d_in[2];
    const float* gamma = (const float*)d_in[3];
    const float* beta  = (const float*)d_in[4];
    const float* Wq    = (const float*)d_in[5];
    const float* bq    = (const float*)d_in[6];
    const float* Wk    = (const float*)d_in[7];
    const float* bk    = (const float*)d_in[8];
    const float* Wv    = (const float*)d_in[9];
    const float* bv    = (const float*)d_in[10];
    const float* Wo    = (const float*)d_in[11];
    const float* bo    = (const float*)d_in[12];
    const float* W1    = (const float*)d_in[13];
    const float* b1    = (const float*)d_in[14];
    const float* W2    = (const float*)d_in[15];
    const float* b2    = (const float*)d_in[16];
    float* out = (float*)d_out;

    float  *h, *h2, *bqkv;
    __half *hLh, *qkv, *ctxh, *fh, *ffnh, *WqkvT, *WoT, *W1T, *W2T;
    cudaGetSymbolAddress((void**)&h,     g_h);
    cudaGetSymbolAddress((void**)&h2,    g_h2);
    cudaGetSymbolAddress((void**)&bqkv,  g_bqkv);
    cudaGetSymbolAddress((void**)&hLh,   g_hLh);
    cudaGetSymbolAddress((void**)&qkv,   g_qkv);
    cudaGetSymbolAddress((void**)&ctxh,  g_ctxh);
    cudaGetSymbolAddress((void**)&fh,    g_fh);
    cudaGetSymbolAddress((void**)&ffnh,  g_ffnh);
    cudaGetSymbolAddress((void**)&WqkvT, g_WqkvT);
    cudaGetSymbolAddress((void**)&WoT,   g_WoT);
    cudaGetSymbolAddress((void**)&W1T,   g_W1T);
    cudaGetSymbolAddress((void**)&W2T,   g_W2T);

    cudaFuncSetAttribute(flash_h,
        cudaFuncAttributeMaxDynamicSharedMemorySize, FL_SMEM);
    cudaFuncSetAttribute(gemm_h<1>,
        cudaFuncAttributeMaxDynamicSharedMemorySize, GEMM_SMEM);
    cudaFuncSetAttribute(gemm_h<2>,
        cudaFuncAttributeMaxDynamicSharedMemorySize, GEMM_SMEM);
    cudaFuncSetAttribute(gemm_h<3>,
        cudaFuncAttributeMaxDynamicSharedMemorySize, GEMM_SMEM);

    dim3 tb(32, 8);

    // 0: input projection + pre-attn LN
    input_ln_kernel<<<Mrows, 256>>>(x, W_in, b_in, gamma, beta, h, hLh);
    // 1: bias concat
    biascat_kernel<<<12, 256>>>(bq, bk, bv, bqkv);
    // 2: qkv weight transpose (fused)
    transpose_qkv<<<dim3(32, 32, 3), tb>>>(Wq, Wk, Wv, WqkvT);
    // 3: fused QKV projection (ncu target)
    gemm_h<3><<<dim3(3*Emb/128, Mrows/64), 128, GEMM_SMEM>>>(
        hLh, WqkvT, bqkv, nullptr, qkv, Mrows, 3*Emb, Emb);
    // 4: fused flash attention -> ctx (half)
    flash_h<<<dim3(Nseq/128, Bsz*Hh), 256, FL_SMEM>>>(qkv, ctxh);
    // 5: Wo transpose
    transpose_h<<<dim3(Emb/32, Emb/32), tb>>>(Wo, WoT, Emb, Emb);
    // 6: O projection + residual (fp32 out)
    gemm_h<2><<<dim3(Emb/128, Mrows/64), 128, GEMM_SMEM>>>(
        ctxh, WoT, bo, h, h2, Mrows, Emb, Emb);
    // 7: LN -> f (half)
    ln_kernel<<<Mrows, 256>>>(h2, gamma, beta, fh);
    // 8: W1 transpose
    transpose_h<<<dim3(FFd/32, Emb/32), tb>>>(W1, W1T, Emb, FFd);
    // 9: FFN1 + gelu (half out)
    gemm_h<1><<<dim3(FFd/128, Mrows/64), 128, GEMM_SMEM>>>(
        fh, W1T, b1, nullptr, ffnh, Mrows, FFd, Emb);
    // 10: W2 transpose
    transpose_h<<<dim3(Emb/32, FFd/32), tb>>>(W2, W2T, FFd, Emb);
    // 11: FFN2 + residual (fp32 out)
    gemm_h<2><<<dim3(Emb/128, Mrows/64), 128, GEMM_SMEM>>>(
        ffnh, W2T, b2, h2, out, Mrows, Emb, FFd);
}

// round 16
// speedup vs baseline: 1.0350x; 1.0135x over previous
#include <cuda_runtime.h>
#include <cuda_fp16.h>
#include <math.h>
#include <stdint.h>

#define Bsz  2
#define Nseq 2048
#define Emb  1024
#define Hh   16
#define Dh   64
#define FFd  4096
#define Mrows (Bsz*Nseq)   // 4096

// ---------------- scratch (module globals; no runtime allocation) ----------
__device__ float  g_h  [Mrows*Emb];          // residual 1 (fp32)
__device__ float  g_h2 [Mrows*Emb];          // residual 2 (fp32)
__device__ __half g_hLh[Mrows*Emb];          // LN1 out (half)
__device__ __half g_qkv[3*(size_t)Mrows*Emb];// q(pre-scaled)/k/v planes [B,H,N,D]
__device__ __half g_ctxh[Mrows*Emb];         // attention out (half)
__device__ __half g_fh [Mrows*Emb];          // LN2 out (half)
__device__ __half g_ffnh[(size_t)Mrows*FFd]; // gelu out (half)
__device__ __half g_WqkvT[3*(size_t)Emb*Emb];// [n][k] K-major, q|k|v
__device__ __half g_WoT[Emb*Emb];
__device__ __half g_W1T[(size_t)Emb*FFd];
__device__ __half g_W2T[(size_t)FFd*Emb];
__device__ float  g_bqkv[3*Emb];

// =================== helpers ================================================
__device__ __forceinline__ uint32_t smem_u32(const void* p) {
    uint32_t a;
    asm("{ .reg .u64 t; cvta.to.shared.u64 t, %1; cvt.u32.u64 %0, t; }"
        : "=r"(a) : "l"(p));
    return a;
}
__device__ __forceinline__ void cp16(uint32_t dst, const void* src) {
    asm volatile("cp.async.cg.shared.global [%0], [%1], 16;" :: "r"(dst), "l"(src));
}
__device__ __forceinline__ void mma_fp16(float d[4], const uint32_t a[4],
                                         const uint32_t b[2]) {
    asm volatile(
        "mma.sync.aligned.m16n8k16.row.col.f32.f16.f16.f32 "
        "{%0,%1,%2,%3}, {%4,%5,%6,%7}, {%8,%9}, {%0,%1,%2,%3};"
        : "+f"(d[0]), "+f"(d[1]), "+f"(d[2]), "+f"(d[3])
        : "r"(a[0]), "r"(a[1]), "r"(a[2]), "r"(a[3]), "r"(b[0]), "r"(b[1]));
}
__device__ __forceinline__ uint32_t packh2(float x, float y) {
    __half2 h = __floats2half2_rn(x, y);
    return *(uint32_t*)&h;
}
__device__ __forceinline__ void ldsm_x4(uint32_t& r0, uint32_t& r1,
                                        uint32_t& r2, uint32_t& r3,
                                        uint32_t addr) {
    asm volatile("ldmatrix.sync.aligned.m8n8.x4.shared.b16 "
                 "{%0,%1,%2,%3}, [%4];"
                 : "=r"(r0), "=r"(r1), "=r"(r2), "=r"(r3) : "r"(addr));
}
__device__ __forceinline__ void ldsm_x4_t(uint32_t& r0, uint32_t& r1,
                                          uint32_t& r2, uint32_t& r3,
                                          uint32_t addr) {
    asm volatile("ldmatrix.sync.aligned.m8n8.x4.trans.shared.b16 "
                 "{%0,%1,%2,%3}, [%4];"
                 : "=r"(r0), "=r"(r1), "=r"(r2), "=r"(r3) : "r"(addr));
}

// ====== fp16 mma GEMM: 64x128 CTA, 128 thr, 32x64 warp tiles (R15 best) =====
// C[M,N] = A[M,K](half) @ Bt^T(half,[N,K] K-major) + bias(fp32)
// MODE 1: gelu -> half    MODE 2: +res -> fp32    MODE 3: qkv scatter -> half
#define SROWH 40   // halfs per smem row (BK 32 + pad 8); ldsm conflict-free
#define ABUF  (64  * SROWH)                 // A halfs per stage
#define BBUF  (128 * SROWH)                 // B halfs per stage
#define GEMM_SMEM (3 * (ABUF + BBUF) * 2)   // 46080 bytes

template<int MODE>
__global__ __launch_bounds__(128, 4) void gemm_h(
    const __half* __restrict__ A, const __half* __restrict__ Bt,
    const float* __restrict__ bias, const float* __restrict__ res,
    void* __restrict__ Cv, int M, int N, int K)
{
    extern __shared__ __half gsm[];
    __half* sA = gsm;                 // [3][ABUF]
    __half* sB = gsm + 3 * ABUF;      // [3][BBUF]

    const int tid  = threadIdx.x;
    const int wid  = tid >> 5;         // 0..3
    const int lane = tid & 31;
    const int gid  = lane >> 2;
    const int tig  = lane & 3;
    const int m_w  = (wid & 1) * 32;   // 2 m-warps
    const int n_w  = (wid >> 1) * 64;  // 2 n-warps (64-wide tiles)
    const int m0   = blockIdx.y * 64;
    const int n0   = blockIdx.x * 128;

    const __half* Ab = A  + (size_t)m0 * K;
    const __half* Bb = Bt + (size_t)n0 * K;

    const int lr = tid >> 2;           // base row
    const int ls = tid & 3;            // 8-half segment

    const int lrow  = lane & 15;        // ldmatrix row within 16
    const int lcolh = (lane >> 4) * 8;  // ldmatrix col offset (halfs)

    const uint32_t sA0 = smem_u32(sA);
    const uint32_t sB0 = smem_u32(sB);
    const uint32_t stgA = ABUF * 2;
    const uint32_t stgBy = BBUF * 2;

    float acc[2][8][4] = {};
    const int nk = K >> 5;              // BK = 32 halfs

    // ---- prologue: prefetch chunks 0 and 1 --------------------------------
    #pragma unroll
    for (int p = 0; p < 2; ++p) {
        const int kk = p << 5;
        const uint32_t da = sA0 + (uint32_t)p * stgA;
        const uint32_t db = sB0 + (uint32_t)p * stgBy;
        #pragma unroll
        for (int j = 0; j < 2; ++j) {
            const int r = lr + j * 32;
            cp16(da + (r * SROWH + ls * 8) * 2, Ab + (size_t)r * K + kk + ls * 8);
        }
        #pragma unroll
        for (int j = 0; j < 4; ++j) {
            const int r = lr + j * 32;
            cp16(db + (r * SROWH + ls * 8) * 2, Bb + (size_t)r * K + kk + ls * 8);
        }
        asm volatile("cp.async.commit_group;");
    }

    int stg = 0;
    for (int c = 0; c < nk; ++c) {
        if (c + 1 < nk) { asm volatile("cp.async.wait_group 1;"); }
        else            { asm volatile("cp.async.wait_group 0;"); }
        __syncthreads();

        if (c + 2 < nk) {
            const int kk = (c + 2) << 5;
            const int ns = (stg + 2 >= 3) ? stg - 1 : stg + 2;
            const uint32_t da = sA0 + (uint32_t)ns * stgA;
            const uint32_t db = sB0 + (uint32_t)ns * stgBy;
            #pragma unroll
            for (int j = 0; j < 2; ++j) {
                const int r = lr + j * 32;
                cp16(da + (r * SROWH + ls * 8) * 2, Ab + (size_t)r * K + kk + ls * 8);
            }
            #pragma unroll
            for (int j = 0; j < 4; ++j) {
                const int r = lr + j * 32;
                cp16(db + (r * SROWH + ls * 8) * 2, Bb + (size_t)r * K + kk + ls * 8);
            }
            asm volatile("cp.async.commit_group;");
        }

        const uint32_t aB = sA0 + (uint32_t)stg * stgA;
        const uint32_t bB = sB0 + (uint32_t)stg * stgBy;

        #pragma unroll
        for (int ks = 0; ks < 2; ++ks) {            // two k16 steps per chunk
            const int kh = ks * 16 + lcolh;
            uint32_t ua[2][4];
            #pragma unroll
            for (int mt = 0; mt < 2; ++mt)
                ldsm_x4(ua[mt][0], ua[mt][1], ua[mt][2], ua[mt][3],
                        aB + ((m_w + mt * 16 + lrow) * SROWH + kh) * 2);
            uint32_t ub[8][2];
            #pragma unroll
            for (int ntp = 0; ntp < 4; ++ntp) {
                uint32_t r0, r1, r2, r3;
                ldsm_x4(r0, r1, r2, r3,
                        bB + ((n_w + ntp * 16 + lrow) * SROWH + kh) * 2);
                ub[2*ntp    ][0] = r0; ub[2*ntp    ][1] = r2;
                ub[2*ntp + 1][0] = r1; ub[2*ntp + 1][1] = r3;
            }
            #pragma unroll
            for (int mt = 0; mt < 2; ++mt)
                #pragma unroll
                for (int nt = 0; nt < 8; ++nt)
                    mma_fp16(acc[mt][nt], ua[mt], ub[nt]);
        }
        stg = (stg + 1 >= 3) ? 0 : stg + 1;
    }

    #pragma unroll
    for (int mt = 0; mt < 2; ++mt) {
        const int row = m0 + m_w + mt * 16 + gid;
        #pragma unroll
        for (int nt = 0; nt < 8; ++nt) {
            const int col = n0 + n_w + nt * 8 + tig * 2;
            float2 b2 = *(const float2*)(bias + col);
            #pragma unroll
            for (int hf = 0; hf < 2; ++hf) {
                const int r = row + hf * 8;
                float vx = acc[mt][nt][hf * 2 + 0] + b2.x;
                float vy = acc[mt][nt][hf * 2 + 1] + b2.y;
                if (MODE == 1) {
                    vx = 0.5f * vx * (1.0f + erff(vx * 0.70710678118654752f));
                    vy = 0.5f * vy * (1.0f + erff(vy * 0.70710678118654752f));
                    *(__half2*)((__half*)Cv + (size_t)r * N + col)
                        = __floats2half2_rn(vx, vy);
                }
                if (MODE == 2) {
                    float2 r2 = *(const float2*)(res + (size_t)r * N + col);
                    float2 o; o.x = vx + r2.x; o.y = vy + r2.y;
                    *(float2*)((float*)Cv + (size_t)r * N + col) = o;
                }
                if (MODE == 3) {
                    const int which = col >> 10;
                    const int cc = col & 1023;
                    const int hh = cc >> 6, dd = cc & 63;
                    if (which == 0) { vx *= 0.03125f; vy *= 0.03125f; }
                    const int b = r >> 11, n = r & 2047;
                    __half* dst = (__half*)Cv +
                        (((size_t)((which * Bsz + b) * Hh + hh)) * Nseq + n) * Dh + dd;
                    *(__half2*)dst = __floats2half2_rn(vx, vy);
                }
            }
        }
    }
}

// =================== fused flash attention (fp16 mma) =======================
// qkv planes (half): q pre-scaled by 1/32. out: ctx (half) [B,N,E].
#define KSTR  72   // halfs per smem row
#define KSTRW 36
#define FL_SMEM ((2*64 + 2*64 + 128) * KSTR * 2)   // 55296 bytes

__global__ __launch_bounds__(256, 2) void flash_h(
    const __half* __restrict__ QKV, __half* __restrict__ ctx)
{
    extern __shared__ __half smh[];
    __half* sK = smh;                    // [2][64*KSTR]
    __half* sV = smh + 2 * 64 * KSTR;    // [2][64*KSTR]
    __half* sQ = smh + 4 * 64 * KSTR;    // [128*KSTR]

    const int tid  = threadIdx.x;
    const int wid  = tid >> 5;
    const int lane = tid & 31;
    const int gid  = lane >> 2;
    const int tig  = lane & 3;
    const int bh   = blockIdx.y;
    const int b    = bh >> 4;
    const int hh   = bh & 15;
    const int m0   = blockIdx.x * 128;

    const size_t PLN = (size_t)Bsz * Hh * Nseq * Dh;
    const __half* Qb = QKV           + ((size_t)bh * Nseq + m0) * Dh;
    const __half* Kb = QKV + PLN     + (size_t)bh * Nseq * Dh;
    const __half* Vb = QKV + 2 * PLN + (size_t)bh * Nseq * Dh;

    // stage Q tile (128 x 64 halfs)
    #pragma unroll
    for (int i = 0; i < 4; ++i) {
        const int idx = i * 256 + tid;
        const int r = idx >> 3, sg = idx & 7;
        *(float4*)(sQ + r * KSTR + sg * 8) = *(const float4*)(Qb + r * Dh + sg * 8);
    }
    __syncthreads();

    uint32_t uq[4][4];
    {
        const uint32_t* q_s = (const uint32_t*)sQ + (wid * 16) * KSTRW;
        #pragma unroll
        for (int ks = 0; ks < 4; ++ks) {
            const int kw = ks * 8;
            uq[ks][0] = q_s[ gid      * KSTRW + kw + tig    ];
            uq[ks][1] = q_s[(gid + 8) * KSTRW + kw + tig    ];
            uq[ks][2] = q_s[ gid      * KSTRW + kw + tig + 4];
            uq[ks][3] = q_s[(gid + 8) * KSTRW + kw + tig + 4];
        }
    }
    __syncthreads();

    float oacc[8][4] = {};
    float mrun[2] = {-1e30f, -1e30f};
    float lrun[2] = {0.0f, 0.0f};

    const uint32_t sK0 = smem_u32(sK);
    const uint32_t sV0 = smem_u32(sV);
    const uint32_t tileB = 64 * KSTR * 2;

    // K/V tile loader: 64 rows x 64 halfs, 2 x 16B per thread per tile
    {
        #pragma unroll
        for (int j = 0; j < 2; ++j) {
            const int idx = j * 256 + tid;
            const int r = idx >> 3, sg = idx & 7;
            cp16(sK0 + (r * KSTR + sg * 8) * 2, Kb + (size_t)r * Dh + sg * 8);
            cp16(sV0 + (r * KSTR + sg * 8) * 2, Vb + (size_t)r * Dh + sg * 8);
        }
        asm volatile("cp.async.commit_group;");
    }

    const int niter = Nseq / 64;
    for (int it = 0; it < niter; ++it) {
        const int buf = it & 1;
        if (it + 1 < niter) {
            const uint32_t dk = sK0 + (uint32_t)((it + 1) & 1) * tileB;
            const uint32_t dv = sV0 + (uint32_t)((it + 1) & 1) * tileB;
            const __half* Kn = Kb + (size_t)(it + 1) * 64 * Dh;
            const __half* Vn = Vb + (size_t)(it + 1) * 64 * Dh;
            #pragma unroll
            for (int j = 0; j < 2; ++j) {
                const int idx = j * 256 + tid;
                const int r = idx >> 3, sg = idx & 7;
                cp16(dk + (r * KSTR + sg * 8) * 2, Kn + (size_t)r * Dh + sg * 8);
                cp16(dv + (r * KSTR + sg * 8) * 2, Vn + (size_t)r * Dh + sg * 8);
            }
            asm volatile("cp.async.commit_group;");
            asm volatile("cp.async.wait_group 1;");
        } else {
            asm volatile("cp.async.wait_group 0;");
        }
        __syncthreads();

        const uint32_t* k_s = (const uint32_t*)(sK + buf * 64 * KSTR);
        const uint32_t  vb  = sV0 + (uint32_t)buf * tileB;

        // ---- S = (Q/32) @ K^T  (scale pre-folded into Q) -----------------
        float sacc[8][4] = {};
        #pragma unroll
        for (int ks = 0; ks < 4; ++ks) {
            const int kw = ks * 8;
            uint32_t ub[8][2];
            #pragma unroll
            for (int nt = 0; nt < 8; ++nt) {
                const int rn = nt * 8 + gid;
                ub[nt][0] = k_s[rn * KSTRW + kw + tig    ];
                ub[nt][1] = k_s[rn * KSTRW + kw + tig + 4];
            }
            #pragma unroll
            for (int nt = 0; nt < 8; ++nt)
                mma_fp16(sacc[nt], uq[ks], ub[nt]);
        }

        // ---- online softmax ----------------------------------------------
        float rm0 = -1e30f, rm1 = -1e30f;
        #pragma unroll
        for (int nt = 0; nt < 8; ++nt) {
            rm0 = fmaxf(rm0, fmaxf(sacc[nt][0], sacc[nt][1]));
            rm1 = fmaxf(rm1, fmaxf(sacc[nt][2], sacc[nt][3]));
        }
        rm0 = fmaxf(rm0, __shfl_xor_sync(0xffffffff, rm0, 1));
        rm0 = fmaxf(rm0, __shfl_xor_sync(0xffffffff, rm0, 2));
        rm1 = fmaxf(rm1, __shfl_xor_sync(0xffffffff, rm1, 1));
        rm1 = fmaxf(rm1, __shfl_xor_sync(0xffffffff, rm1, 2));

        const float mn0 = fmaxf(mrun[0], rm0);
        const float mn1 = fmaxf(mrun[1], rm1);
        const float cor0 = __expf(mrun[0] - mn0);
        const float cor1 = __expf(mrun[1] - mn1);
        mrun[0] = mn0; mrun[1] = mn1;

        float rs0 = 0.0f, rs1 = 0.0f;
        #pragma unroll
        for (int nt = 0; nt < 8; ++nt) {
            sacc[nt][0] = __expf(sacc[nt][0] - mn0);
            sacc[nt][1] = __expf(sacc[nt][1] - mn0);
            sacc[nt][2] = __expf(sacc[nt][2] - mn1);
            sacc[nt][3] = __expf(sacc[nt][3] - mn1);
            rs0 += sacc[nt][0] + sacc[nt][1];
            rs1 += sacc[nt][2] + sacc[nt][3];
        }
        rs0 += __shfl_xor_sync(0xffffffff, rs0, 1);
        rs0 += __shfl_xor_sync(0xffffffff, rs0, 2);
        rs1 += __shfl_xor_sync(0xffffffff, rs1, 1);
        rs1 += __shfl_xor_sync(0xffffffff, rs1, 2);

        lrun[0] = lrun[0] * cor0 + rs0;
        lrun[1] = lrun[1] * cor1 + rs1;
        #pragma unroll
        for (int dt = 0; dt < 8; ++dt) {
            oacc[dt][0] *= cor0; oacc[dt][1] *= cor0;
            oacc[dt][2] *= cor1; oacc[dt][3] *= cor1;
        }

        // ---- O += P @ V : P C-frags repacked as A-frags in registers -------
        #pragma unroll
        for (int ks2 = 0; ks2 < 4; ++ks2) {
            uint32_t pa[4];
            pa[0] = packh2(sacc[2*ks2    ][0], sacc[2*ks2    ][1]);
            pa[1] = packh2(sacc[2*ks2    ][2], sacc[2*ks2    ][3]);
            pa[2] = packh2(sacc[2*ks2 + 1][0], sacc[2*ks2 + 1][1]);
            pa[3] = packh2(sacc[2*ks2 + 1][2], sacc[2*ks2 + 1][3]);
            const int t  = lane >> 3;
            const int rr = lane & 7;
            #pragma unroll
            for (int ntp = 0; ntp < 4; ++ntp) {
                const uint32_t addr = vb +
                    ((ks2 * 16 + (t & 1) * 8 + rr) * KSTR + ntp * 16 + (t >> 1) * 8) * 2;
                uint32_t r0, r1, r2, r3;
                ldsm_x4_t(r0, r1, r2, r3, addr);
                uint32_t bb0[2] = {r0, r1};
                uint32_t bb1[2] = {r2, r3};
                mma_fp16(oacc[2*ntp    ], pa, bb0);
                mma_fp16(oacc[2*ntp + 1], pa, bb1);
            }
        }
        __syncthreads();
    }

    // ---- epilogue: O /= l -> half, write ctx [B,N,E] -------------------------
    const float li0 = 1.0f / lrun[0];
    const float li1 = 1.0f / lrun[1];
    const int row0 = m0 + wid * 16 + gid;
    #pragma unroll
    for (int dt = 0; dt < 8; ++dt) {
        const int col = hh * Dh + dt * 8 + tig * 2;
        *(__half2*)(ctx + ((size_t)(b * Nseq + row0    )) * Emb + col)
            = __floats2half2_rn(oacc[dt][0] * li0, oacc[dt][1] * li0);
        *(__half2*)(ctx + ((size_t)(b * Nseq + row0 + 8)) * Emb + col)
            = __floats2half2_rn(oacc[dt][2] * li1, oacc[dt][3] * li1);
    }
}

// =================== weight transposes (fp32 -> half, [n][k]) ===============
__global__ void transpose_h(const float* __restrict__ W,
                            __half* __restrict__ Wt, int K, int N)
{
    __shared__ float tile[32][33];
    const int n0 = blockIdx.x * 32, k0 = blockIdx.y * 32;
    const int tx = threadIdx.x, ty = threadIdx.y;  // 32 x 8
    #pragma unroll
    for (int i = 0; i < 32; i += 8)
        tile[ty + i][tx] = W[(size_t)(k0 + ty + i) * N + n0 + tx];
    __syncthreads();
    #pragma unroll
    for (int i = 0; i < 32; i += 8)
        Wt[(size_t)(n0 + ty + i) * K + k0 + tx] = __float2half_rn(tile[tx][ty + i]);
}

__global__ void transpose_qkv(const float* __restrict__ Wq,
                              const float* __restrict__ Wk,
                              const float* __restrict__ Wv,
                              __half* __restrict__ Wt)
{
    const float* W = blockIdx.z == 0 ? Wq : (blockIdx.z == 1 ? Wk : Wv);
    __half* dst = Wt + (size_t)blockIdx.z * Emb * Emb;
    __shared__ float tile[32][33];
    const int n0 = blockIdx.x * 32, k0 = blockIdx.y * 32;
    const int tx = threadIdx.x, ty = threadIdx.y;
    #pragma unroll
    for (int i = 0; i < 32; i += 8)
        tile[ty + i][tx] = W[(size_t)(k0 + ty + i) * Emb + n0 + tx];
    __syncthreads();
    #pragma unroll
    for (int i = 0; i < 32; i += 8)
        dst[(size_t)(n0 + ty + i) * Emb + k0 + tx] = __float2half_rn(tile[tx][ty + i]);
}

__global__ void biascat_kernel(const float* __restrict__ bq,
                               const float* __restrict__ bk,
                               const float* __restrict__ bv,
                               float* __restrict__ dst)
{
    const int i = blockIdx.x * 256 + threadIdx.x;
    dst[i] = i < 1024 ? bq[i] : (i < 2048 ? bk[i - 1024] : bv[i - 2048]);
}

// ---------------- block-wide mean/var via warp shuffles ---------------------
__device__ __forceinline__ void blk_meanvar(float s, float q, int tid,
                                            float& mean, float& var)
{
    __shared__ float ws[8], wq[8];
    #pragma unroll
    for (int o = 16; o > 0; o >>= 1) {
        s += __shfl_xor_sync(0xffffffff, s, o);
        q += __shfl_xor_sync(0xffffffff, q, o);
    }
    if ((tid & 31) == 0) { ws[tid >> 5] = s; wq[tid >> 5] = q; }
    __syncthreads();
    float ss = ws[tid & 7], qq = wq[tid & 7];
    #pragma unroll
    for (int o = 4; o > 0; o >>= 1) {
        ss += __shfl_xor_sync(0xffffffff, ss, o);
        qq += __shfl_xor_sync(0xffffffff, qq, o);
    }
    mean = ss * (1.0f / Emb);
    var  = qq * (1.0f / Emb) - mean * mean;
}

// ---------------- input proj (K=2) + LayerNorm ------------------------------
__global__ void input_ln_kernel(const float* __restrict__ x,
                                const float* __restrict__ Wi,
                                const float* __restrict__ bi,
                                const float* __restrict__ gamma,
                                const float* __restrict__ beta,
                                float* __restrict__ h,
                                __half* __restrict__ hL)
{
    const int m = blockIdx.x;
    const int t = threadIdx.x;
    const float x0 = x[m*2+0];
    const float x1 = x[m*2+1];
    const int c = t*4;

    float4 w0 = *(const float4*)(Wi + c);
    float4 w1 = *(const float4*)(Wi + Emb + c);
    float4 bb = *(const float4*)(bi + c);

    float v0 = fmaf(x0,w0.x, fmaf(x1,w1.x, bb.x));
    float v1 = fmaf(x0,w0.y, fmaf(x1,w1.y, bb.y));
    float v2 = fmaf(x0,w0.z, fmaf(x1,w1.z, bb.z));
    float v3 = fmaf(x0,w0.w, fmaf(x1,w1.w, bb.w));

    *(float4*)(h + (size_t)m*Emb + c) = make_float4(v0,v1,v2,v3);

    float mean, var;
    blk_meanvar(v0+v1+v2+v3, v0*v0+v1*v1+v2*v2+v3*v3, t, mean, var);
    const float rs = rsqrtf(var + 1e-5f);

    float4 g4 = *(const float4*)(gamma + c);
    float4 b4 = *(const float4*)(beta  + c);
    __half* dst = hL + (size_t)m*Emb + c;
    *(__half2*)(dst    ) = __floats2half2_rn((v0-mean)*rs*g4.x + b4.x,
                                             (v1-mean)*rs*g4.y + b4.y);
    *(__half2*)(dst + 2) = __floats2half2_rn((v2-mean)*rs*g4.z + b4.z,
                                             (v3-mean)*rs*g4.w + b4.w);
}

// ---------------- LayerNorm (fp32 in -> half out) ----------------------------
__global__ void ln_kernel(const float* __restrict__ X,
                          const float* __restrict__ gamma,
                          const float* __restrict__ beta,
                          __half* __restrict__ Y)
{
    const int m = blockIdx.x;
    const int t = threadIdx.x;
    const int c = t*4;
    float4 v = *(const float4*)(X + (size_t)m*Emb + c);

    float mean, var;
    blk_meanvar(v.x+v.y+v.z+v.w, v.x*v.x+v.y*v.y+v.z*v.z+v.w*v.w, t, mean, var);
    const float rs = rsqrtf(var + 1e-5f);

    float4 g4 = *(const float4*)(gamma + c);
    float4 b4 = *(const float4*)(beta  + c);
    __half* dst = Y + (size_t)m*Emb + c;
    *(__half2*)(dst    ) = __floats2half2_rn((v.x-mean)*rs*g4.x + b4.x,
                                             (v.y-mean)*rs*g4.y + b4.y);
    *(__half2*)(dst + 2) = __floats2half2_rn((v.z-mean)*rs*g4.z + b4.z,
                                             (v.w-mean)*rs*g4.w + b4.w);
}

// ---------------- launch ----------------------------------------------------
extern "C" void kernel_launch(void* const* d_in, const int* in_sizes, int n_in,
                              void* d_out, int out_size)
{
    (void)in_sizes; (void)n_in; (void)out_size;
    const float* x     = (const float*)d_in[0];
    const float* W_in  = (const float*)d_in[1];
    const float* b_in  = (const float*)d_in[2];
    const float* gamma = (const float*)d_in[3];
    const float* beta  = (const float*)d_in[4];
    const float* Wq    = (const float*)d_in[5];
    const float* bq    = (const float*)d_in[6];
    const float* Wk    = (const float*)d_in[7];
    const float* bk    = (const float*)d_in[8];
    const float* Wv    = (const float*)d_in[9];
    const float* bv    = (const float*)d_in[10];
    const float* Wo    = (const float*)d_in[11];
    const float* bo    = (const float*)d_in[12];
    const float* W1    = (const float*)d_in[13];
    const float* b1    = (const float*)d_in[14];
    const float* W2    = (const float*)d_in[15];
    const float* b2    = (const float*)d_in[16];
    float* out = (float*)d_out;

    float  *h, *h2, *bqkv;
    __half *hLh, *qkv, *ctxh, *fh, *ffnh, *WqkvT, *WoT, *W1T, *W2T;
    cudaGetSymbolAddress((void**)&h,     g_h);
    cudaGetSymbolAddress((void**)&h2,    g_h2);
    cudaGetSymbolAddress((void**)&bqkv,  g_bqkv);
    cudaGetSymbolAddress((void**)&hLh,   g_hLh);
    cudaGetSymbolAddress((void**)&qkv,   g_qkv);
    cudaGetSymbolAddress((void**)&ctxh,  g_ctxh);
    cudaGetSymbolAddress((void**)&fh,    g_fh);
    cudaGetSymbolAddress((void**)&ffnh,  g_ffnh);
    cudaGetSymbolAddress((void**)&WqkvT, g_WqkvT);
    cudaGetSymbolAddress((void**)&WoT,   g_WoT);
    cudaGetSymbolAddress((void**)&W1T,   g_W1T);
    cudaGetSymbolAddress((void**)&W2T,   g_W2T);

    cudaFuncSetAttribute(flash_h,
        cudaFuncAttributeMaxDynamicSharedMemorySize, FL_SMEM);
    cudaFuncSetAttribute(gemm_h<1>,
        cudaFuncAttributeMaxDynamicSharedMemorySize, GEMM_SMEM);
    cudaFuncSetAttribute(gemm_h<2>,
        cudaFuncAttributeMaxDynamicSharedMemorySize, GEMM_SMEM);
    cudaFuncSetAttribute(gemm_h<3>,
        cudaFuncAttributeMaxDynamicSharedMemorySize, GEMM_SMEM);

    dim3 tb(32, 8);

    // side stream + events (kernel_launch runs only twice: correctness+capture;
    // per-call creation is deterministic and capture-legal via fork/join events)
    cudaStream_t s2;
    cudaStreamCreateWithFlags(&s2, cudaStreamNonBlocking);
    cudaEvent_t evFork, evQKV, evW;
    cudaEventCreateWithFlags(&evFork, cudaEventDisableTiming);
    cudaEventCreateWithFlags(&evQKV,  cudaEventDisableTiming);
    cudaEventCreateWithFlags(&evW,    cudaEventDisableTiming);

    // fork: s2 joins the capture graph
    cudaEventRecord(evFork, 0);
    cudaStreamWaitEvent(s2, evFork, 0);

    // --- side stream: input-only weight prep ---------------------------------
    biascat_kernel<<<12, 256, 0, s2>>>(bq, bk, bv, bqkv);
    transpose_qkv<<<dim3(32, 32, 3), tb, 0, s2>>>(Wq, Wk, Wv, WqkvT);
    cudaEventRecord(evQKV, s2);
    transpose_h<<<dim3(Emb/32, Emb/32), tb, 0, s2>>>(Wo, WoT, Emb, Emb);
    transpose_h<<<dim3(FFd/32, Emb/32), tb, 0, s2>>>(W1, W1T, Emb, FFd);
    transpose_h<<<dim3(Emb/32, FFd/32), tb, 0, s2>>>(W2, W2T, FFd, Emb);
    cudaEventRecord(evW, s2);

    // --- main stream ----------------------------------------------------------
    // 0: input projection + pre-attn LN (overlaps side stream)
    input_ln_kernel<<<Mrows, 256>>>(x, W_in, b_in, gamma, beta, h, hLh);
    // join: QKV weights ready
    cudaStreamWaitEvent(0, evQKV, 0);
    // 1: fused QKV projection
    gemm_h<3><<<dim3(3*Emb/128, Mrows/64), 128, GEMM_SMEM>>>(
        hLh, WqkvT, bqkv, nullptr, qkv, Mrows, 3*Emb, Emb);
    // 2: fused flash attention -> ctx (half)  (remaining transposes overlap)
    flash_h<<<dim3(Nseq/128, Bsz*Hh), 256, FL_SMEM>>>(qkv, ctxh);
    // join: Wo/W1/W2 ready
    cudaStreamWaitEvent(0, evW, 0);
    // 3: O projection + residual (fp32 out)
    gemm_h<2><<<dim3(Emb/128, Mrows/64), 128, GEMM_SMEM>>>(
        ctxh, WoT, bo, h, h2, Mrows, Emb, Emb);
    // 4: LN -> f (half)
    ln_kernel<<<Mrows, 256>>>(h2, gamma, beta, fh);
    // 5: FFN1 + gelu (half out)
    gemm_h<1><<<dim3(FFd/128, Mrows/64), 128, GEMM_SMEM>>>(
        fh, W1T, b1, nullptr, ffnh, Mrows, FFd, Emb);
    // 6: FFN2 + residual (fp32 out)
    gemm_h<2><<<dim3(Emb/128, Mrows/64), 128, GEMM_SMEM>>>(
        ffnh, W2T, b2, h2, out, Mrows, Emb, FFd);
}